// round 2
// baseline (speedup 1.0000x reference)
#include <cuda_runtime.h>

// Newton-Schulz orthogonalization, X in R^{2048 x 512}, fp32.
// Restructured: one Gram + one update per iteration; residual from the Gram.
// f32x2 packed-FMA GEMMs (2x scalar FFMA throughput on sm_103a).
// Device-side early stop (graph-capturable, deterministic).

#define D_DIM 2048
#define M_DIM 512
#define NSTEPS 20
#define EPS_F 1e-6f
#define SPLITK 8
#define KC (D_DIM / SPLITK)   // 256

__device__ float g_X [D_DIM * M_DIM];
__device__ float g_X2[D_DIM * M_DIM];
__device__ float g_Gp[SPLITK][M_DIM * M_DIM];
__device__ float g_G [M_DIM * M_DIM];
__device__ float g_rpart[256];
__device__ int   g_done;
__device__ int   g_cur;   // which buffer holds the current iterate (0 = g_X)

typedef unsigned long long ull;

__device__ __forceinline__ ull dup2(float x) {
    unsigned u = __float_as_uint(x);
    return ((ull)u << 32) | (ull)u;
}
__device__ __forceinline__ float lo2(ull x) { return __uint_as_float((unsigned)x); }
__device__ __forceinline__ float hi2(ull x) { return __uint_as_float((unsigned)(x >> 32)); }
__device__ __forceinline__ void ffma2(ull& d, ull a, ull b) {
    asm("fma.rn.f32x2 %0, %1, %2, %0;" : "+l"(d) : "l"(a), "l"(b));
}

// ---------------------------------------------------------------- init
__global__ void __launch_bounds__(256) init_kernel(const float* __restrict__ x) {
    int idx = blockIdx.x * blockDim.x + threadIdx.x;
    const float4* src = (const float4*)x;
    float4* dst = (float4*)g_X;
    const int n4 = D_DIM * M_DIM / 4;
    for (int i = idx; i < n4; i += gridDim.x * blockDim.x) dst[i] = src[i];
    if (idx == 0) { g_done = 0; g_cur = 0; }
}

// ---------------------------------------------------------------- gram: Gp[z] = X^T X (k-slice)
// grid (4,4,SPLITK): 128x128 tile, K-chunk 256. 256 thr, 8x8 per thread via f32x2.
__global__ void __launch_bounds__(256) gram_kernel(int sel) {
    if (g_done) return;
    const float* __restrict__ Xin = sel ? g_X2 : g_X;
    __shared__ __align__(16) float As[16][128];
    __shared__ __align__(16) float Bsd[16][8][32];   // duplicated vp-plane layout
    const int i0 = blockIdx.x * 128;
    const int j0 = blockIdx.y * 128;
    const int k0 = blockIdx.z * KC;
    const int tid = threadIdx.x;
    const int tx = tid & 15;
    const int ty = tid >> 4;

    ull acc[4][8];
#pragma unroll
    for (int up = 0; up < 4; up++)
#pragma unroll
        for (int v = 0; v < 8; v++) acc[up][v] = 0ull;

    for (int kc = 0; kc < KC; kc += 16) {
#pragma unroll
        for (int l = 0; l < 2; l++) {
            int id = tid + l * 256;          // 512 ids: 16 rows x 32 float4
            int r  = id >> 5;
            int c  = (id & 31) << 2;
            const float* rowp = &Xin[(size_t)(k0 + kc + r) * M_DIM];
            float4 a = *(const float4*)&rowp[i0 + c];
            float4 b = *(const float4*)&rowp[j0 + c];
            *(float4*)&As[r][c] = a;
            int j = c >> 3, v = c & 7;       // v in {0,4}
            *(ull*)&Bsd[r][v + 0][2 * j] = dup2(b.x);
            *(ull*)&Bsd[r][v + 1][2 * j] = dup2(b.y);
            *(ull*)&Bsd[r][v + 2][2 * j] = dup2(b.z);
            *(ull*)&Bsd[r][v + 3][2 * j] = dup2(b.w);
        }
        __syncthreads();
#pragma unroll
        for (int kk = 0; kk < 16; kk++) {
            ull ap[4], bp[8];
#pragma unroll
            for (int up = 0; up < 4; up++)
                ap[up] = *(const ull*)&As[kk][ty * 8 + 2 * up];
#pragma unroll
            for (int v = 0; v < 8; v++)
                bp[v] = *(const ull*)&Bsd[kk][v][2 * tx];
#pragma unroll
            for (int up = 0; up < 4; up++)
#pragma unroll
                for (int v = 0; v < 8; v++)
                    ffma2(acc[up][v], ap[up], bp[v]);
        }
        __syncthreads();
    }

    float* out = g_Gp[blockIdx.z];
#pragma unroll
    for (int up = 0; up < 4; up++) {
#pragma unroll
        for (int h = 0; h < 2; h++) {
            int row = i0 + ty * 8 + 2 * up + h;
            float w[8];
#pragma unroll
            for (int v = 0; v < 8; v++) w[v] = h ? hi2(acc[up][v]) : lo2(acc[up][v]);
            *(float4*)&out[(size_t)row * M_DIM + j0 + tx * 8] =
                make_float4(w[0], w[1], w[2], w[3]);
            *(float4*)&out[(size_t)row * M_DIM + j0 + tx * 8 + 4] =
                make_float4(w[4], w[5], w[6], w[7]);
        }
    }
}

// ---------------------------------------------------------------- reduce: G = sum_z Gp[z]; residual partials
__global__ void __launch_bounds__(256) reduce_kernel() {
    if (g_done) return;
    const int idx = blockIdx.x * 256 + threadIdx.x;   // 65536 threads x 4 elems
    const int p = idx * 4;
    float4 s = make_float4(0.f, 0.f, 0.f, 0.f);
#pragma unroll
    for (int z = 0; z < SPLITK; z++) {
        float4 v = *(const float4*)&g_Gp[z][p];
        s.x += v.x; s.y += v.y; s.z += v.z; s.w += v.w;
    }
    *(float4*)&g_G[p] = s;
    const int row = p >> 9;
    const int col = p & 511;
    float e0 = ((row == col + 0) ? 1.f : 0.f) - s.x;
    float e1 = ((row == col + 1) ? 1.f : 0.f) - s.y;
    float e2 = ((row == col + 2) ? 1.f : 0.f) - s.z;
    float e3 = ((row == col + 3) ? 1.f : 0.f) - s.w;
    float local = e0 * e0 + e1 * e1 + e2 * e2 + e3 * e3;

    __shared__ float red[256];
    red[threadIdx.x] = local;
    __syncthreads();
    for (int off = 128; off > 0; off >>= 1) {
        if (threadIdx.x < off) red[threadIdx.x] += red[threadIdx.x + off];
        __syncthreads();
    }
    if (threadIdx.x == 0) g_rpart[blockIdx.x] = red[0];
}

// ---------------------------------------------------------------- check: set g_done if converged
__global__ void check_kernel(int step) {
    if (g_done) return;
    float s = 0.f;
    for (int i = threadIdx.x; i < 256; i += 32) s += g_rpart[i];
#pragma unroll
    for (int off = 16; off > 0; off >>= 1) s += __shfl_down_sync(0xffffffffu, s, off);
    if (threadIdx.x == 0 && step >= 1 && s <= EPS_F) g_done = 1;
}

// ---------------------------------------------------------------- update: Xout = Xin * (1.5I - 0.5G)
// grid (16,8): 128x64 tile, K=512. 256 thr, 8x4 per thread via f32x2.
__global__ void __launch_bounds__(256) update_kernel(int sel) {
    if (g_done) return;
    const float* __restrict__ Xin  = sel ? g_X2 : g_X;
    float* __restrict__ Xout       = sel ? g_X  : g_X2;
    __shared__ __align__(16) float As[16][132];      // transposed X tile: As[k][row]
    __shared__ __align__(16) float Bsd[16][4][32];   // W tile, duplicated vp-plane layout
    const int i0 = blockIdx.x * 128;
    const int c0 = blockIdx.y * 64;
    const int tid = threadIdx.x;
    const int tx = tid & 15;
    const int ty = tid >> 4;

    ull acc[4][4];
#pragma unroll
    for (int up = 0; up < 4; up++)
#pragma unroll
        for (int v = 0; v < 4; v++) acc[up][v] = 0ull;

    for (int k0 = 0; k0 < M_DIM; k0 += 16) {
#pragma unroll
        for (int l = 0; l < 2; l++) {
            int id = tid + l * 256;       // 512 ids: 128 rows x 4 float4
            int r  = id >> 2;
            int kb = (id & 3) << 2;
            float4 v = *(const float4*)&Xin[(size_t)(i0 + r) * M_DIM + k0 + kb];
            As[kb + 0][r] = v.x;
            As[kb + 1][r] = v.y;
            As[kb + 2][r] = v.z;
            As[kb + 3][r] = v.w;
        }
        {
            int r  = tid >> 4;            // 0..15
            int cb = (tid & 15) << 2;     // 0..60
            int grow = k0 + r;
            float4 v = *(const float4*)&g_G[(size_t)grow * M_DIM + c0 + cb];
            float w0 = ((grow == c0 + cb + 0) ? 1.5f : 0.f) - 0.5f * v.x;
            float w1 = ((grow == c0 + cb + 1) ? 1.5f : 0.f) - 0.5f * v.y;
            float w2 = ((grow == c0 + cb + 2) ? 1.5f : 0.f) - 0.5f * v.z;
            float w3 = ((grow == c0 + cb + 3) ? 1.5f : 0.f) - 0.5f * v.w;
            int j = cb >> 2;              // = tx
            *(ull*)&Bsd[r][0][2 * j] = dup2(w0);
            *(ull*)&Bsd[r][1][2 * j] = dup2(w1);
            *(ull*)&Bsd[r][2][2 * j] = dup2(w2);
            *(ull*)&Bsd[r][3][2 * j] = dup2(w3);
        }
        __syncthreads();
#pragma unroll
        for (int kk = 0; kk < 16; kk++) {
            ull ap[4], bp[4];
#pragma unroll
            for (int up = 0; up < 4; up++)
                ap[up] = *(const ull*)&As[kk][ty * 8 + 2 * up];
#pragma unroll
            for (int v = 0; v < 4; v++)
                bp[v] = *(const ull*)&Bsd[kk][v][2 * tx];
#pragma unroll
            for (int up = 0; up < 4; up++)
#pragma unroll
                for (int v = 0; v < 4; v++)
                    ffma2(acc[up][v], ap[up], bp[v]);
        }
        __syncthreads();
    }

#pragma unroll
    for (int up = 0; up < 4; up++) {
#pragma unroll
        for (int h = 0; h < 2; h++) {
            int row = i0 + ty * 8 + 2 * up + h;
            float4 o = h ? make_float4(hi2(acc[up][0]), hi2(acc[up][1]),
                                       hi2(acc[up][2]), hi2(acc[up][3]))
                         : make_float4(lo2(acc[up][0]), lo2(acc[up][1]),
                                       lo2(acc[up][2]), lo2(acc[up][3]));
            *(float4*)&Xout[(size_t)row * M_DIM + c0 + tx * 4] = o;
        }
    }
    if (tid == 0 && blockIdx.x == 0 && blockIdx.y == 0) g_cur = sel ^ 1;
}

// ---------------------------------------------------------------- emit result
__global__ void __launch_bounds__(256) final_kernel(float* __restrict__ out) {
    int idx = blockIdx.x * blockDim.x + threadIdx.x;
    float4* dst = (float4*)out;
    const float4* src = g_cur ? (const float4*)g_X2 : (const float4*)g_X;
    const int n4 = D_DIM * M_DIM / 4;
    for (int i = idx; i < n4; i += gridDim.x * blockDim.x) dst[i] = src[i];
}

extern "C" void kernel_launch(void* const* d_in, const int* in_sizes, int n_in,
                              void* d_out, int out_size) {
    const float* x = (const float*)d_in[0];
    float* out = (float*)d_out;
    (void)in_sizes; (void)n_in; (void)out_size;

    init_kernel<<<256, 256>>>(x);
    for (int k = 0; k < NSTEPS; k++) {
        int sel = k & 1;
        gram_kernel<<<dim3(4, 4, SPLITK), 256>>>(sel);
        reduce_kernel<<<256, 256>>>();
        check_kernel<<<1, 32>>>(k);
        update_kernel<<<dim3(16, 8), 256>>>(sel);
    }
    final_kernel<<<256, 256>>>(out);
}

// round 5
// speedup vs baseline: 1.0227x; 1.0227x over previous
#include <cuda_runtime.h>
#include <cstdint>

// Newton-Schulz orthogonalization, X in R^{2048x512}, fp32 via 3xTF32 mma.sync.
// Operands kept as (hi,lo) tf32 pairs, interleaved in memory so each fragment
// load is one conflict-free LDS.128. Early stop via device flag.

#define D_DIM 2048
#define M_DIM 512
#define NSTEPS 20
#define EPS_F 1e-6f

// interleaved (h,l): element e occupies words 2e, 2e+1
__device__ __align__(16) float g_Xi [2][D_DIM * M_DIM * 2];  // row-major [d][c]
__device__ __align__(16) float g_XTi[2][M_DIM * D_DIM * 2];  // row-major [c][d]
__device__ __align__(16) float g_Wi [M_DIM * M_DIM * 2];
__device__ __align__(16) float g_Gp [8][M_DIM * M_DIM];
__device__ float g_rpart[256];
__device__ int   g_done;
__device__ int   g_cur;
__device__ int   g_cnt;

#define SA_STR 68          // smem words per row: 32 elems * 2 + 4 pad
#define A_TILE_W (128 * SA_STR)

__device__ __forceinline__ uint32_t smem_u32(const void* p) {
    uint32_t a;
    asm("{ .reg .u64 t; cvta.to.shared.u64 t, %1; cvt.u32.u64 %0, t; }" : "=r"(a) : "l"(p));
    return a;
}
__device__ __forceinline__ float tf32_rna(float x) {
    uint32_t u;
    asm("cvt.rna.tf32.f32 %0, %1;" : "=r"(u) : "f"(x));
    return __uint_as_float(u);
}
__device__ __forceinline__ void lds128(uint32_t& r0, uint32_t& r1, uint32_t& r2,
                                       uint32_t& r3, uint32_t addr) {
    asm volatile("ld.shared.v4.u32 {%0, %1, %2, %3}, [%4];"
                 : "=r"(r0), "=r"(r1), "=r"(r2), "=r"(r3) : "r"(addr));
}
__device__ __forceinline__ void mma8(float* acc,
                                     uint32_t a0, uint32_t a1, uint32_t a2, uint32_t a3,
                                     uint32_t b0, uint32_t b1) {
    asm volatile("mma.sync.aligned.m16n8k8.row.col.f32.tf32.tf32.f32 "
                 "{%0,%1,%2,%3}, {%4,%5,%6,%7}, {%8,%9}, {%0,%1,%2,%3};"
                 : "+f"(acc[0]), "+f"(acc[1]), "+f"(acc[2]), "+f"(acc[3])
                 : "r"(a0), "r"(a1), "r"(a2), "r"(a3), "r"(b0), "r"(b1));
}
// 3xTF32 accumulate. a[h][0..3] = words (hi,lo,hi,lo) of k-slot0/slot1 at row
// block h (h=0 -> rows g, h=1 -> rows g+8). b[0..3] = (hi,lo,hi,lo) likewise.
// PTX A order: (g,s0), (g+8,s0), (g,s1), (g+8,s1).
__device__ __forceinline__ void mma3x(float* c, const uint32_t a[2][4], const uint32_t b[4]) {
    mma8(c, a[0][0], a[1][0], a[0][2], a[1][2], b[0], b[2]);  // hh
    mma8(c, a[0][0], a[1][0], a[0][2], a[1][2], b[1], b[3]);  // hl
    mma8(c, a[0][1], a[1][1], a[0][3], a[1][3], b[0], b[2]);  // lh
}

// ---------------------------------------------------------------- init
__global__ void __launch_bounds__(256) init_kernel(const float* __restrict__ x) {
    int idx = blockIdx.x * blockDim.x + threadIdx.x;
    const float4* x4 = (const float4*)x;
    const int n4 = D_DIM * M_DIM / 4;
    for (int i = idx; i < n4; i += gridDim.x * blockDim.x) {
        float4 v = x4[i];
        int e0 = i * 4;
        int d = e0 >> 9;
        int c = e0 & (M_DIM - 1);
        float h0 = tf32_rna(v.x), l0 = tf32_rna(v.x - h0);
        float h1 = tf32_rna(v.y), l1 = tf32_rna(v.y - h1);
        float h2 = tf32_rna(v.z), l2 = tf32_rna(v.z - h2);
        float h3 = tf32_rna(v.w), l3 = tf32_rna(v.w - h3);
        *(float4*)&g_Xi[0][(size_t)e0 * 2]     = make_float4(h0, l0, h1, l1);
        *(float4*)&g_Xi[0][(size_t)e0 * 2 + 4] = make_float4(h2, l2, h3, l3);
        *(float2*)&g_XTi[0][((size_t)(c + 0) * D_DIM + d) * 2] = make_float2(h0, l0);
        *(float2*)&g_XTi[0][((size_t)(c + 1) * D_DIM + d) * 2] = make_float2(h1, l1);
        *(float2*)&g_XTi[0][((size_t)(c + 2) * D_DIM + d) * 2] = make_float2(h2, l2);
        *(float2*)&g_XTi[0][((size_t)(c + 3) * D_DIM + d) * 2] = make_float2(h3, l3);
    }
    if (idx == 0) { g_done = 0; g_cur = 0; g_cnt = 0; }
}

// ---------------------------------------------------------------- gram
// Gp[z][i,j] = sum_{k chunk z} XT[i,k]*XT[j,k]. grid (4,4,8), 256 thr.
// CTA tile 128x128, K-chunk 256 in 8 stages of 32. Warps 2(m) x 4(n).
__global__ void __launch_bounds__(256) gram_kernel(int sel) {
    if (g_done) return;
    extern __shared__ __align__(16) float smem[];
    float* As = smem;
    float* Bs = smem + A_TILE_W;
    const int tid = threadIdx.x, lane = tid & 31, wid = tid >> 5;
    const int wm = wid >> 2, wn = wid & 3, g = lane >> 2, t = lane & 3;
    const int i0 = blockIdx.x * 128, j0 = blockIdx.y * 128, k0 = blockIdx.z * 256;
    const float* __restrict__ XT = g_XTi[sel];
    const uint32_t sb = smem_u32(smem);

    float acc[4][4][4] = {};

    for (int st = 0; st < 8; st++) {
        __syncthreads();
        const int kc = k0 + st * 32;
#pragma unroll
        for (int l = 0; l < 16; l++) {
            int id = tid + l * 256;
            int tile = id >> 11, rem = id & 2047, r = rem >> 4, f = rem & 15;
            int grow = (tile ? j0 : i0) + r;
            float4 v = *(const float4*)&XT[(size_t)grow * (2 * D_DIM) + kc * 2 + f * 4];
            *(float4*)((tile ? Bs : As) + r * SA_STR + f * 4) = v;
        }
        __syncthreads();
#pragma unroll
        for (int ks = 0; ks < 4; ks++) {
            uint32_t a[4][2][4];
#pragma unroll
            for (int mt = 0; mt < 4; mt++)
#pragma unroll
                for (int h = 0; h < 2; h++) {
                    int row = wm * 64 + mt * 16 + h * 8 + g;
                    lds128(a[mt][h][0], a[mt][h][1], a[mt][h][2], a[mt][h][3],
                           sb + (row * SA_STR + ks * 16 + t * 4) * 4);
                }
#pragma unroll
            for (int nt = 0; nt < 4; nt++) {
                uint32_t b[4];
                int row = wn * 32 + nt * 8 + g;
                lds128(b[0], b[1], b[2], b[3],
                       sb + (A_TILE_W + row * SA_STR + ks * 16 + t * 4) * 4);
#pragma unroll
                for (int mt = 0; mt < 4; mt++)
                    mma3x(acc[mt][nt], a[mt], b);
            }
        }
    }

    float* out = g_Gp[blockIdx.z];
#pragma unroll
    for (int mt = 0; mt < 4; mt++) {
#pragma unroll
        for (int nt = 0; nt < 4; nt++) {
            int r0 = i0 + wm * 64 + mt * 16 + g;
            int cc = j0 + wn * 32 + nt * 8 + t * 2;
            *(float2*)&out[(size_t)r0 * M_DIM + cc] =
                make_float2(acc[mt][nt][0], acc[mt][nt][1]);
            *(float2*)&out[(size_t)(r0 + 8) * M_DIM + cc] =
                make_float2(acc[mt][nt][2], acc[mt][nt][3]);
        }
    }
}

// ---------------------------------------------------------------- reduce + W + residual + check
__global__ void __launch_bounds__(256) reduce_kernel(int step) {
    if (g_done) return;
    const int idx = blockIdx.x * 256 + threadIdx.x;
    const int p = idx * 4;
    float4 s = make_float4(0.f, 0.f, 0.f, 0.f);
#pragma unroll
    for (int z = 0; z < 8; z++) {
        float4 v = *(const float4*)&g_Gp[z][p];
        s.x += v.x; s.y += v.y; s.z += v.z; s.w += v.w;
    }
    const int row = p >> 9;
    const int col = p & 511;
    float gv[4] = { s.x, s.y, s.z, s.w };
    float wh[4], wl[4];
    float local = 0.f;
#pragma unroll
    for (int q = 0; q < 4; q++) {
        float iv = (row == col + q) ? 1.f : 0.f;
        float e = iv - gv[q];
        local += e * e;
        float w = ((row == col + q) ? 1.5f : 0.f) - 0.5f * gv[q];
        float h = tf32_rna(w);
        wh[q] = h;
        wl[q] = tf32_rna(w - h);
    }
    *(float4*)&g_Wi[(size_t)p * 2]     = make_float4(wh[0], wl[0], wh[1], wl[1]);
    *(float4*)&g_Wi[(size_t)p * 2 + 4] = make_float4(wh[2], wl[2], wh[3], wl[3]);

    __shared__ float red[256];
    red[threadIdx.x] = local;
    __syncthreads();
    for (int off = 128; off > 0; off >>= 1) {
        if (threadIdx.x < off) red[threadIdx.x] += red[threadIdx.x + off];
        __syncthreads();
    }
    __shared__ int is_last;
    if (threadIdx.x == 0) {
        g_rpart[blockIdx.x] = red[0];
        __threadfence();
        int tkt = atomicAdd(&g_cnt, 1);
        is_last = (tkt == gridDim.x - 1);
    }
    __syncthreads();
    if (is_last && threadIdx.x == 0) {
        float tot = 0.f;
        for (int i = 0; i < 256; i++) {
            float v;
            asm volatile("ld.global.cg.f32 %0, [%1];" : "=f"(v) : "l"(&g_rpart[i]));
            tot += v;
        }
        if (step >= 1 && tot <= EPS_F) g_done = 1;
        g_cnt = 0;
    }
}

// ---------------------------------------------------------------- update
// XT_new[c,d] = sum_m W[c,m]*X[d,m] (W symmetric). grid (4,32), 256 thr.
// CTA tile 128c x 64d, K=512 in 16 stages of 32. Warps 2(m=c) x 4(n=d,16 each).
__global__ void __launch_bounds__(256) update_kernel(int sel) {
    if (g_done) return;
    extern __shared__ __align__(16) float smem[];
    float* As = smem;                    // W tile 128 x 32
    float* Bs = smem + A_TILE_W;         // X tile  64 x 32
    const int tid = threadIdx.x, lane = tid & 31, wid = tid >> 5;
    const int wm = wid >> 2, wn = wid & 3, g = lane >> 2, t = lane & 3;
    const int c0 = blockIdx.x * 128, d0 = blockIdx.y * 64;
    const float* __restrict__ Xin = g_Xi[sel];
    const uint32_t sb = smem_u32(smem);

    float acc[4][2][4] = {};

    for (int st = 0; st < 16; st++) {
        __syncthreads();
        const int kc = st * 32;
#pragma unroll
        for (int l = 0; l < 12; l++) {
            int id = tid + l * 256;
            if (id < 2048) {            // A: 128 rows x 16 float4
                int r = id >> 4, f = id & 15;
                float4 v = *(const float4*)&g_Wi[(size_t)(c0 + r) * (2 * M_DIM) + kc * 2 + f * 4];
                *(float4*)(As + r * SA_STR + f * 4) = v;
            } else {                    // B: 64 rows x 16 float4
                int id2 = id - 2048;
                int r = id2 >> 4, f = id2 & 15;
                float4 v = *(const float4*)&Xin[(size_t)(d0 + r) * (2 * M_DIM) + kc * 2 + f * 4];
                *(float4*)(Bs + r * SA_STR + f * 4) = v;
            }
        }
        __syncthreads();
#pragma unroll
        for (int ks = 0; ks < 4; ks++) {
            uint32_t a[4][2][4];
#pragma unroll
            for (int mt = 0; mt < 4; mt++)
#pragma unroll
                for (int h = 0; h < 2; h++) {
                    int row = wm * 64 + mt * 16 + h * 8 + g;
                    lds128(a[mt][h][0], a[mt][h][1], a[mt][h][2], a[mt][h][3],
                           sb + (row * SA_STR + ks * 16 + t * 4) * 4);
                }
#pragma unroll
            for (int nt = 0; nt < 2; nt++) {
                uint32_t b[4];
                int row = wn * 16 + nt * 8 + g;
                lds128(b[0], b[1], b[2], b[3],
                       sb + (A_TILE_W + row * SA_STR + ks * 16 + t * 4) * 4);
#pragma unroll
                for (int mt = 0; mt < 4; mt++)
                    mma3x(acc[mt][nt], a[mt], b);
            }
        }
    }

    const int os = sel ^ 1;
    float* __restrict__ XTo = g_XTi[os];
    float* __restrict__ Xo  = g_Xi[os];
#pragma unroll
    for (int mt = 0; mt < 4; mt++) {
#pragma unroll
        for (int nt = 0; nt < 2; nt++) {
#pragma unroll
            for (int h = 0; h < 2; h++) {
                int c = c0 + wm * 64 + mt * 16 + h * 8 + g;
                int d = d0 + wn * 16 + nt * 8 + t * 2;
                float v0 = acc[mt][nt][h * 2 + 0];
                float v1 = acc[mt][nt][h * 2 + 1];
                float h0 = tf32_rna(v0), l0 = tf32_rna(v0 - h0);
                float h1 = tf32_rna(v1), l1 = tf32_rna(v1 - h1);
                *(float4*)&XTo[((size_t)c * D_DIM + d) * 2] = make_float4(h0, l0, h1, l1);
                *(float2*)&Xo[((size_t)(d + 0) * M_DIM + c) * 2] = make_float2(h0, l0);
                *(float2*)&Xo[((size_t)(d + 1) * M_DIM + c) * 2] = make_float2(h1, l1);
            }
        }
    }
    if (tid == 0 && blockIdx.x == 0 && blockIdx.y == 0) g_cur = os;
}

// ---------------------------------------------------------------- emit result
__global__ void __launch_bounds__(256) final_kernel(float* __restrict__ out) {
    const float2* src = (const float2*)g_Xi[g_cur];
    int idx = blockIdx.x * blockDim.x + threadIdx.x;
    for (int i = idx; i < D_DIM * M_DIM; i += gridDim.x * blockDim.x) {
        float2 v = src[i];
        out[i] = v.x + v.y;
    }
}

extern "C" void kernel_launch(void* const* d_in, const int* in_sizes, int n_in,
                              void* d_out, int out_size) {
    const float* x = (const float*)d_in[0];
    float* out = (float*)d_out;
    (void)in_sizes; (void)n_in; (void)out_size;

    const int gram_smem   = 2 * A_TILE_W * 4;              // 69632
    const int update_smem = (A_TILE_W + 64 * SA_STR) * 4;  // 52224
    cudaFuncSetAttribute(gram_kernel,   cudaFuncAttributeMaxDynamicSharedMemorySize, gram_smem);
    cudaFuncSetAttribute(update_kernel, cudaFuncAttributeMaxDynamicSharedMemorySize, update_smem);

    init_kernel<<<512, 256>>>(x);
    for (int k = 0; k < NSTEPS; k++) {
        int sel = k & 1;
        gram_kernel<<<dim3(4, 4, 8), 256, gram_smem>>>(sel);
        reduce_kernel<<<256, 256>>>(k);
        update_kernel<<<dim3(4, 32), 256, update_smem>>>(sel);
    }
    final_kernel<<<512, 256>>>(out);
}

// round 6
// speedup vs baseline: 1.0820x; 1.0580x over previous
#include <cuda_runtime.h>
#include <cstdint>

// Newton-Schulz orthogonalization, X in R^{2048x512}, fp32 via 3xTF32 mma.sync.
// (hi,lo) tf32 pairs interleaved so fragment loads are single conflict-free
// LDS.128. GEMMs use a 2-stage cp.async pipeline. Early stop via device flag.

#define D_DIM 2048
#define M_DIM 512
#define NSTEPS 20
#define EPS_F 1e-6f

// interleaved (h,l): element e occupies words 2e, 2e+1
__device__ __align__(16) float g_Xi [2][D_DIM * M_DIM * 2];  // row-major [d][c]
__device__ __align__(16) float g_XTi[2][M_DIM * D_DIM * 2];  // row-major [c][d]
__device__ __align__(16) float g_Wi [M_DIM * M_DIM * 2];
__device__ __align__(16) float g_Gp [8][M_DIM * M_DIM];
__device__ float g_rpart[256];
__device__ int   g_done;
__device__ int   g_cur;
__device__ int   g_cnt;

#define SA_STR 68                    // smem words per row: 32 elems * 2 + 4 pad
#define A_TILE_W (128 * SA_STR)      // 8704 words
#define B64_TILE_W (64 * SA_STR)     // 4352 words
#define G_STAGE_W (2 * A_TILE_W)     // gram stage: A+B tiles, 17408 words
#define U_STAGE_W (A_TILE_W + B64_TILE_W)  // update stage: 13056 words

__device__ __forceinline__ uint32_t smem_u32(const void* p) {
    uint32_t a;
    asm("{ .reg .u64 t; cvta.to.shared.u64 t, %1; cvt.u32.u64 %0, t; }" : "=r"(a) : "l"(p));
    return a;
}
__device__ __forceinline__ float tf32_rna(float x) {
    uint32_t u;
    asm("cvt.rna.tf32.f32 %0, %1;" : "=r"(u) : "f"(x));
    return __uint_as_float(u);
}
__device__ __forceinline__ void cp16(uint32_t dst, const void* src) {
    asm volatile("cp.async.cg.shared.global [%0], [%1], 16;" :: "r"(dst), "l"(src) : "memory");
}
__device__ __forceinline__ void cp_commit() {
    asm volatile("cp.async.commit_group;" ::: "memory");
}
__device__ __forceinline__ void lds128(uint32_t& r0, uint32_t& r1, uint32_t& r2,
                                       uint32_t& r3, uint32_t addr) {
    asm volatile("ld.shared.v4.u32 {%0, %1, %2, %3}, [%4];"
                 : "=r"(r0), "=r"(r1), "=r"(r2), "=r"(r3) : "r"(addr));
}
__device__ __forceinline__ void mma8(float* acc,
                                     uint32_t a0, uint32_t a1, uint32_t a2, uint32_t a3,
                                     uint32_t b0, uint32_t b1) {
    asm volatile("mma.sync.aligned.m16n8k8.row.col.f32.tf32.tf32.f32 "
                 "{%0,%1,%2,%3}, {%4,%5,%6,%7}, {%8,%9}, {%0,%1,%2,%3};"
                 : "+f"(acc[0]), "+f"(acc[1]), "+f"(acc[2]), "+f"(acc[3])
                 : "r"(a0), "r"(a1), "r"(a2), "r"(a3), "r"(b0), "r"(b1));
}
// 3xTF32. a[h][0..3] = (hi,lo,hi,lo) words of k-slot0/1, row block h (g / g+8).
// PTX A order: (g,s0), (g+8,s0), (g,s1), (g+8,s1).
__device__ __forceinline__ void mma3x(float* c, const uint32_t a[2][4], const uint32_t b[4]) {
    mma8(c, a[0][0], a[1][0], a[0][2], a[1][2], b[0], b[2]);  // hh
    mma8(c, a[0][0], a[1][0], a[0][2], a[1][2], b[1], b[3]);  // hl
    mma8(c, a[0][1], a[1][1], a[0][3], a[1][3], b[0], b[2]);  // lh
}

// ---------------------------------------------------------------- init
__global__ void __launch_bounds__(256) init_kernel(const float* __restrict__ x) {
    int idx = blockIdx.x * blockDim.x + threadIdx.x;
    const float4* x4 = (const float4*)x;
    const int n4 = D_DIM * M_DIM / 4;
    for (int i = idx; i < n4; i += gridDim.x * blockDim.x) {
        float4 v = x4[i];
        int e0 = i * 4;
        int d = e0 >> 9;
        int c = e0 & (M_DIM - 1);
        float h0 = tf32_rna(v.x), l0 = tf32_rna(v.x - h0);
        float h1 = tf32_rna(v.y), l1 = tf32_rna(v.y - h1);
        float h2 = tf32_rna(v.z), l2 = tf32_rna(v.z - h2);
        float h3 = tf32_rna(v.w), l3 = tf32_rna(v.w - h3);
        *(float4*)&g_Xi[0][(size_t)e0 * 2]     = make_float4(h0, l0, h1, l1);
        *(float4*)&g_Xi[0][(size_t)e0 * 2 + 4] = make_float4(h2, l2, h3, l3);
        *(float2*)&g_XTi[0][((size_t)(c + 0) * D_DIM + d) * 2] = make_float2(h0, l0);
        *(float2*)&g_XTi[0][((size_t)(c + 1) * D_DIM + d) * 2] = make_float2(h1, l1);
        *(float2*)&g_XTi[0][((size_t)(c + 2) * D_DIM + d) * 2] = make_float2(h2, l2);
        *(float2*)&g_XTi[0][((size_t)(c + 3) * D_DIM + d) * 2] = make_float2(h3, l3);
    }
    if (idx == 0) { g_done = 0; g_cur = 0; g_cnt = 0; }
}

// ---------------------------------------------------------------- gram
// Gp[z][i,j] = sum_{k chunk z} XT[i,k]*XT[j,k]. grid (4,4,8), 256 thr.
// CTA tile 128x128, K-chunk 256 in 8 stages of 32, 2-stage cp.async pipeline.
__global__ void __launch_bounds__(256) gram_kernel(int sel) {
    if (g_done) return;
    extern __shared__ __align__(16) float smem[];
    const int tid = threadIdx.x, lane = tid & 31, wid = tid >> 5;
    const int wm = wid >> 2, wn = wid & 3, g = lane >> 2, t = lane & 3;
    const int i0 = blockIdx.x * 128, j0 = blockIdx.y * 128, k0 = blockIdx.z * 256;
    const float* __restrict__ XT = g_XTi[sel];
    const uint32_t sb = smem_u32(smem);

    auto load_stage = [&](int st, int buf) {
        const int kc = k0 + st * 32;
#pragma unroll
        for (int l = 0; l < 16; l++) {
            int id = tid + l * 256;
            int tile = id >> 11, rem = id & 2047, r = rem >> 4, f = rem & 15;
            int grow = (tile ? j0 : i0) + r;
            const float* src = &XT[(size_t)grow * (2 * D_DIM) + kc * 2 + f * 4];
            uint32_t dst = sb + (buf * G_STAGE_W + tile * A_TILE_W + r * SA_STR + f * 4) * 4;
            cp16(dst, src);
        }
        cp_commit();
    };

    load_stage(0, 0);
    load_stage(1, 1);

    float acc[4][4][4] = {};

    for (int st = 0; st < 8; st++) {
        if (st < 7) asm volatile("cp.async.wait_group 1;" ::: "memory");
        else        asm volatile("cp.async.wait_group 0;" ::: "memory");
        __syncthreads();
        const uint32_t base = sb + (st & 1) * G_STAGE_W * 4;
#pragma unroll
        for (int ks = 0; ks < 4; ks++) {
            uint32_t a[4][2][4];
#pragma unroll
            for (int mt = 0; mt < 4; mt++)
#pragma unroll
                for (int h = 0; h < 2; h++) {
                    int row = wm * 64 + mt * 16 + h * 8 + g;
                    lds128(a[mt][h][0], a[mt][h][1], a[mt][h][2], a[mt][h][3],
                           base + (row * SA_STR + ks * 16 + t * 4) * 4);
                }
#pragma unroll
            for (int nt = 0; nt < 4; nt++) {
                uint32_t b[4];
                int row = wn * 32 + nt * 8 + g;
                lds128(b[0], b[1], b[2], b[3],
                       base + (A_TILE_W + row * SA_STR + ks * 16 + t * 4) * 4);
#pragma unroll
                for (int mt = 0; mt < 4; mt++)
                    mma3x(acc[mt][nt], a[mt], b);
            }
        }
        __syncthreads();
        if (st + 2 < 8) load_stage(st + 2, st & 1);
    }

    float* out = g_Gp[blockIdx.z];
#pragma unroll
    for (int mt = 0; mt < 4; mt++) {
#pragma unroll
        for (int nt = 0; nt < 4; nt++) {
            int r0 = i0 + wm * 64 + mt * 16 + g;
            int cc = j0 + wn * 32 + nt * 8 + t * 2;
            *(float2*)&out[(size_t)r0 * M_DIM + cc] =
                make_float2(acc[mt][nt][0], acc[mt][nt][1]);
            *(float2*)&out[(size_t)(r0 + 8) * M_DIM + cc] =
                make_float2(acc[mt][nt][2], acc[mt][nt][3]);
        }
    }
}

// ---------------------------------------------------------------- reduce + W + residual + check
__global__ void __launch_bounds__(256) reduce_kernel(int step) {
    if (g_done) return;
    const int idx = blockIdx.x * 256 + threadIdx.x;
    const int p = idx * 4;
    float4 s = make_float4(0.f, 0.f, 0.f, 0.f);
#pragma unroll
    for (int z = 0; z < 8; z++) {
        float4 v = *(const float4*)&g_Gp[z][p];
        s.x += v.x; s.y += v.y; s.z += v.z; s.w += v.w;
    }
    const int row = p >> 9;
    const int col = p & 511;
    float gv[4] = { s.x, s.y, s.z, s.w };
    float wh[4], wl[4];
    float local = 0.f;
#pragma unroll
    for (int q = 0; q < 4; q++) {
        float iv = (row == col + q) ? 1.f : 0.f;
        float e = iv - gv[q];
        local += e * e;
        float w = ((row == col + q) ? 1.5f : 0.f) - 0.5f * gv[q];
        float h = tf32_rna(w);
        wh[q] = h;
        wl[q] = tf32_rna(w - h);
    }
    *(float4*)&g_Wi[(size_t)p * 2]     = make_float4(wh[0], wl[0], wh[1], wl[1]);
    *(float4*)&g_Wi[(size_t)p * 2 + 4] = make_float4(wh[2], wl[2], wh[3], wl[3]);

    __shared__ float red[256];
    red[threadIdx.x] = local;
    __syncthreads();
    for (int off = 128; off > 0; off >>= 1) {
        if (threadIdx.x < off) red[threadIdx.x] += red[threadIdx.x + off];
        __syncthreads();
    }
    __shared__ int is_last;
    if (threadIdx.x == 0) {
        g_rpart[blockIdx.x] = red[0];
        __threadfence();
        int tkt = atomicAdd(&g_cnt, 1);
        is_last = (tkt == gridDim.x - 1);
    }
    __syncthreads();
    if (is_last && threadIdx.x == 0) {
        float tot = 0.f;
        for (int i = 0; i < 256; i++) {
            float v;
            asm volatile("ld.global.cg.f32 %0, [%1];" : "=f"(v) : "l"(&g_rpart[i]));
            tot += v;
        }
        if (step >= 1 && tot <= EPS_F) g_done = 1;
        g_cnt = 0;
    }
}

// ---------------------------------------------------------------- update
// XT_new[c,d] = sum_m W[c,m]*X[d,m] (W symmetric). grid (4,32), 256 thr.
// CTA tile 128c x 64d, K=512 in 16 stages of 32, 2-stage cp.async pipeline.
__global__ void __launch_bounds__(256) update_kernel(int sel) {
    if (g_done) return;
    extern __shared__ __align__(16) float smem[];
    const int tid = threadIdx.x, lane = tid & 31, wid = tid >> 5;
    const int wm = wid >> 2, wn = wid & 3, g = lane >> 2, t = lane & 3;
    const int c0 = blockIdx.x * 128, d0 = blockIdx.y * 64;
    const float* __restrict__ Xin = g_Xi[sel];
    const uint32_t sb = smem_u32(smem);

    auto load_stage = [&](int st, int buf) {
        const int kc = st * 32;
        const uint32_t bb = sb + buf * U_STAGE_W * 4;
#pragma unroll
        for (int l = 0; l < 12; l++) {
            int id = tid + l * 256;
            if (id < 2048) {            // A: W tile, 128 rows x 16 float4
                int r = id >> 4, f = id & 15;
                const float* src = &g_Wi[(size_t)(c0 + r) * (2 * M_DIM) + kc * 2 + f * 4];
                cp16(bb + (r * SA_STR + f * 4) * 4, src);
            } else {                    // B: X tile, 64 rows x 16 float4
                int id2 = id - 2048;
                int r = id2 >> 4, f = id2 & 15;
                const float* src = &Xin[(size_t)(d0 + r) * (2 * M_DIM) + kc * 2 + f * 4];
                cp16(bb + (A_TILE_W + r * SA_STR + f * 4) * 4, src);
            }
        }
        cp_commit();
    };

    load_stage(0, 0);
    load_stage(1, 1);

    float acc[4][2][4] = {};

    for (int st = 0; st < 16; st++) {
        if (st < 15) asm volatile("cp.async.wait_group 1;" ::: "memory");
        else         asm volatile("cp.async.wait_group 0;" ::: "memory");
        __syncthreads();
        const uint32_t base = sb + (st & 1) * U_STAGE_W * 4;
#pragma unroll
        for (int ks = 0; ks < 4; ks++) {
            uint32_t a[4][2][4];
#pragma unroll
            for (int mt = 0; mt < 4; mt++)
#pragma unroll
                for (int h = 0; h < 2; h++) {
                    int row = wm * 64 + mt * 16 + h * 8 + g;
                    lds128(a[mt][h][0], a[mt][h][1], a[mt][h][2], a[mt][h][3],
                           base + (row * SA_STR + ks * 16 + t * 4) * 4);
                }
#pragma unroll
            for (int nt = 0; nt < 2; nt++) {
                uint32_t b[4];
                int row = wn * 16 + nt * 8 + g;
                lds128(b[0], b[1], b[2], b[3],
                       base + (A_TILE_W + row * SA_STR + ks * 16 + t * 4) * 4);
#pragma unroll
                for (int mt = 0; mt < 4; mt++)
                    mma3x(acc[mt][nt], a[mt], b);
            }
        }
        __syncthreads();
        if (st + 2 < 16) load_stage(st + 2, st & 1);
    }

    const int os = sel ^ 1;
    float* __restrict__ XTo = g_XTi[os];
    float* __restrict__ Xo  = g_Xi[os];
#pragma unroll
    for (int mt = 0; mt < 4; mt++) {
#pragma unroll
        for (int nt = 0; nt < 2; nt++) {
#pragma unroll
            for (int h = 0; h < 2; h++) {
                int c = c0 + wm * 64 + mt * 16 + h * 8 + g;
                int d = d0 + wn * 16 + nt * 8 + t * 2;
                float v0 = acc[mt][nt][h * 2 + 0];
                float v1 = acc[mt][nt][h * 2 + 1];
                float h0 = tf32_rna(v0), l0 = tf32_rna(v0 - h0);
                float h1 = tf32_rna(v1), l1 = tf32_rna(v1 - h1);
                *(float4*)&XTo[((size_t)c * D_DIM + d) * 2] = make_float4(h0, l0, h1, l1);
                *(float2*)&Xo[((size_t)(d + 0) * M_DIM + c) * 2] = make_float2(h0, l0);
                *(float2*)&Xo[((size_t)(d + 1) * M_DIM + c) * 2] = make_float2(h1, l1);
            }
        }
    }
    if (tid == 0 && blockIdx.x == 0 && blockIdx.y == 0) g_cur = os;
}

// ---------------------------------------------------------------- emit result
__global__ void __launch_bounds__(256) final_kernel(float* __restrict__ out) {
    const float2* src = (const float2*)g_Xi[g_cur];
    int idx = blockIdx.x * blockDim.x + threadIdx.x;
    for (int i = idx; i < D_DIM * M_DIM; i += gridDim.x * blockDim.x) {
        float2 v = src[i];
        out[i] = v.x + v.y;
    }
}

extern "C" void kernel_launch(void* const* d_in, const int* in_sizes, int n_in,
                              void* d_out, int out_size) {
    const float* x = (const float*)d_in[0];
    float* out = (float*)d_out;
    (void)in_sizes; (void)n_in; (void)out_size;

    const int gram_smem   = 2 * G_STAGE_W * 4;   // 139264
    const int update_smem = 2 * U_STAGE_W * 4;   // 104448
    cudaFuncSetAttribute(gram_kernel,   cudaFuncAttributeMaxDynamicSharedMemorySize, gram_smem);
    cudaFuncSetAttribute(update_kernel, cudaFuncAttributeMaxDynamicSharedMemorySize, update_smem);

    init_kernel<<<512, 256>>>(x);
    for (int k = 0; k < NSTEPS; k++) {
        int sel = k & 1;
        gram_kernel<<<dim3(4, 4, 8), 256, gram_smem>>>(sel);
        reduce_kernel<<<256, 256>>>(k);
        update_kernel<<<dim3(4, 32), 256, update_smem>>>(sel);
    }
    final_kernel<<<512, 256>>>(out);
}